// round 4
// baseline (speedup 1.0000x reference)
#include <cuda_runtime.h>
#include <cstdint>

#define NA 261888
#define TOPK 1000
#define POST 300

// ---------------- static scratch (no allocations allowed) ----------------
__device__ float              g_x[(size_t)2 * 256 * 256 * 256]; // conv output, reused per level
__device__ float              g_scores[2 * NA];
__device__ float4             g_boxes[2 * NA];
__device__ unsigned           g_hist[2][65536];
__device__ unsigned           g_selHi[2];
__device__ unsigned           g_above[2];
__device__ unsigned           g_T[2];
__device__ int                g_candCnt[2];
__device__ unsigned long long g_cand[2][2048];
__device__ float              g_ts[2][1024];
__device__ float4             g_tb[2][1024];

// ---------------- XLA-exact sigmoid: 0.5 + 0.5*fast_tanh(0.5*x) ----------------
// LogisticExpander rewrites logistic(x) -> 0.5 + 0.5*tanh(0.5*x); f32 tanh is
// EmitFastTanh (Eigen rational polynomial), all ops unfused fp32.
__device__ __forceinline__ float xla_fast_tanh(float x) {
    const float kBound = 7.90531110763549805f;
    float xc = fminf(fmaxf(x, -kBound), kBound);
    float x2 = __fmul_rn(xc, xc);
    float n = __fadd_rn(__fmul_rn(x2, -2.76076847742355e-16f), 2.00018790482477e-13f);
    n = __fadd_rn(__fmul_rn(x2, n), -8.60467152213735e-11f);
    n = __fadd_rn(__fmul_rn(x2, n),  5.12229709037114e-08f);
    n = __fadd_rn(__fmul_rn(x2, n),  1.48572235717979e-05f);
    n = __fadd_rn(__fmul_rn(x2, n),  6.37261928875436e-04f);
    n = __fadd_rn(__fmul_rn(x2, n),  4.89352455891786e-03f);
    n = __fmul_rn(xc, n);
    float d = __fadd_rn(__fmul_rn(x2, 1.19825839466702e-06f), 1.18534705686654e-04f);
    d = __fadd_rn(__fmul_rn(x2, d), 2.26843463243900e-03f);
    d = __fadd_rn(__fmul_rn(x2, d), 4.89352518554385e-03f);
    float t = __fdiv_rn(n, d);
    return (fabsf(x) < 0.0004f) ? x : t;
}
__device__ __forceinline__ float xla_sigmoid(float l) {
    float t = xla_fast_tanh(__fmul_rn(0.5f, l));
    return __fadd_rn(0.5f, __fmul_rn(0.5f, t));
}

// ---------------- conv 3x3 (256->256) + bias + relu ----------------
// Sequential FMA per accumulator in (c, ky, kx) ascending order — matches
// cuDNN fp32 implicit-GEMM k-ordering (filter KCRS layout).
__global__ void conv3x3_relu_kernel(const float* __restrict__ in,
                                    const float* __restrict__ w,
                                    const float* __restrict__ bias,
                                    int H, int W) {
    const int tx  = threadIdx.x & 31;
    const int ty  = threadIdx.x >> 5;
    const int x0  = blockIdx.x * 64;
    const int y0  = blockIdx.y * 2;
    const int b   = blockIdx.z >> 3;
    const int ocb = (blockIdx.z & 7) * 32;

    __shared__ float s_in[8][4][66];
    __shared__ float s_w[8][32][9];

    float acc[4][4];
#pragma unroll
    for (int i = 0; i < 4; i++)
#pragma unroll
        for (int j = 0; j < 4; j++) acc[i][j] = 0.f;

    const float* inB = in + (size_t)b * 256 * H * W;

    for (int icb = 0; icb < 256; icb += 8) {
        for (int e = threadIdx.x; e < 8 * 4 * 66; e += 256) {
            int ic = e / 264; int rem = e % 264; int r = rem / 66; int c = rem % 66;
            int yy = y0 + r - 1; int xx = x0 + c - 1;
            float v = 0.f;
            if (yy >= 0 && yy < H && xx >= 0 && xx < W)
                v = inB[(size_t)(icb + ic) * H * W + (size_t)yy * W + xx];
            s_in[ic][r][c] = v;
        }
        for (int e = threadIdx.x; e < 8 * 32 * 9; e += 256) {
            int oc = e / 72; int rem = e % 72; int ic = rem / 9; int k = rem % 9;
            s_w[ic][oc][k] = w[((size_t)(ocb + oc) * 256 + (size_t)(icb + ic)) * 9 + k];
        }
        __syncthreads();
#pragma unroll
        for (int ic = 0; ic < 8; ic++) {
            float va[4][3], vb[4][3];
#pragma unroll
            for (int r = 0; r < 4; r++)
#pragma unroll
                for (int c = 0; c < 3; c++) {
                    va[r][c] = s_in[ic][r][tx + c];
                    vb[r][c] = s_in[ic][r][tx + 32 + c];
                }
#pragma unroll
            for (int k4 = 0; k4 < 4; k4++) {
                const int oc = ty + 8 * k4;
                float w9[9];
#pragma unroll
                for (int k = 0; k < 9; k++) w9[k] = s_w[ic][oc][k];
#pragma unroll
                for (int r = 0; r < 2; r++) {
#pragma unroll
                    for (int ky = 0; ky < 3; ky++)
#pragma unroll
                        for (int kx = 0; kx < 3; kx++) {
                            acc[k4][r * 2 + 0] += va[r + ky][kx] * w9[ky * 3 + kx];
                            acc[k4][r * 2 + 1] += vb[r + ky][kx] * w9[ky * 3 + kx];
                        }
                }
            }
        }
        __syncthreads();
    }
#pragma unroll
    for (int k4 = 0; k4 < 4; k4++) {
        int oc = ocb + ty + 8 * k4;
        float bv = bias[oc];
#pragma unroll
        for (int r = 0; r < 2; r++) {
            int y = y0 + r;
            float* outp = g_x + (size_t)(b * 256 + oc) * H * W + (size_t)y * W;
            int xA = x0 + tx, xB = x0 + 32 + tx;
            if (xA < W) outp[xA] = fmaxf(__fadd_rn(acc[k4][r * 2 + 0], bv), 0.f);
            if (xB < W) outp[xB] = fmaxf(__fadd_rn(acc[k4][r * 2 + 1], bv), 0.f);
        }
    }
}

// ---------------- 1x1 heads + anchor decode + sigmoid + mask ----------------
__global__ void head_decode_kernel(const float* __restrict__ clsw, const float* __restrict__ clsb,
                                   const float* __restrict__ boxw, const float* __restrict__ boxb,
                                   int H, int W, int stride, float asize, int lvl_off) {
    __shared__ float s_cw[3 * 256];
    __shared__ float s_bw[12 * 256];
    for (int e = threadIdx.x; e < 3 * 256; e += blockDim.x) s_cw[e] = clsw[e];
    for (int e = threadIdx.x; e < 12 * 256; e += blockDim.x) s_bw[e] = boxw[e];
    __syncthreads();

    int pix = blockIdx.x * blockDim.x + threadIdx.x;
    int b   = blockIdx.y;
    int HW  = H * W;
    if (pix >= HW) return;

    const float* xp = g_x + (size_t)b * 256 * HW + pix;
    float o[3]  = {0.f, 0.f, 0.f};
    float d[12];
#pragma unroll
    for (int j = 0; j < 12; j++) d[j] = 0.f;

    // pure dot first (sequential FMA, c ascending) ...
    for (int c = 0; c < 256; c++) {
        float v = xp[(size_t)c * HW];
        o[0] += v * s_cw[c];
        o[1] += v * s_cw[256 + c];
        o[2] += v * s_cw[512 + c];
#pragma unroll
        for (int j = 0; j < 12; j++) d[j] += v * s_bw[j * 256 + c];
    }
    // ... bias added afterwards, like the reference's separate "+ b" op
#pragma unroll
    for (int a = 0; a < 3; a++) o[a] = __fadd_rn(o[a], clsb[a]);
#pragma unroll
    for (int j = 0; j < 12; j++) d[j] = __fadd_rn(d[j], boxb[j]);

    int yy = pix / W, xx = pix % W;
    float xs = (float)(xx * stride), ys = (float)(yy * stride);
    const float ratios[3] = {0.5f, 1.0f, 2.0f};
#pragma unroll
    for (int a = 0; a < 3; a++) {
        // anchors in pure fp32, exactly as numpy float32 builds them
        float s  = sqrtf(ratios[a]);
        float hh = __fmul_rn(asize, s);      // size * sqrt(ratio)
        float ww = __fdiv_rn(asize, s);      // size / sqrt(ratio)
        float ax1 = __fadd_rn(xs, -0.5f * ww);   // shifts + base (fp32 add; halving exact)
        float ax2 = __fadd_rn(xs,  0.5f * ww);
        float ay1 = __fadd_rn(ys, -0.5f * hh);
        float ay2 = __fadd_rn(ys,  0.5f * hh);
        float aw = __fsub_rn(ax2, ax1);
        float ah = __fsub_rn(ay2, ay1);
        float ax = __fadd_rn(ax1, 0.5f * aw);
        float ay = __fadd_rn(ay1, 0.5f * ah);
        float dx = d[4 * a], dy = d[4 * a + 1], dw = d[4 * a + 2], dh = d[4 * a + 3];
        // unfused mul+add, matching XLA's separate HLO ops
        float cx = __fadd_rn(__fmul_rn(dx, aw), ax);
        float cy = __fadd_rn(__fmul_rn(dy, ah), ay);
        float pw = __fmul_rn(expf(dw), aw);
        float ph = __fmul_rn(expf(dh), ah);
        float x1 = __fsub_rn(cx, 0.5f * pw);
        float y1 = __fsub_rn(cy, 0.5f * ph);
        float x2 = __fadd_rn(cx, 0.5f * pw);
        float y2 = __fadd_rn(cy, 0.5f * ph);
        x1 = fminf(fmaxf(x1, 0.f), 1024.f);
        y1 = fminf(fmaxf(y1, 0.f), 1024.f);
        x2 = fminf(fmaxf(x2, 0.f), 1024.f);
        y2 = fminf(fmaxf(y2, 0.f), 1024.f);
        float ws = __fsub_rn(x2, x1), hs = __fsub_rn(y2, y1);
        bool valid = (ws >= 1.0f) && (hs >= 1.0f);
        float sc = xla_sigmoid(o[a]);
        float masked = valid ? sc : -1e9f;
        int aidx = lvl_off + pix * 3 + a;
        g_scores[(size_t)b * NA + aidx] = masked;
        g_boxes[(size_t)b * NA + aidx] = make_float4(x1, y1, x2, y2);
    }
}

// ---------------- top-k via 2-pass 16-bit radix select ----------------
__device__ __forceinline__ unsigned f2u(float f) {
    unsigned u = __float_as_uint(f);
    return (u & 0x80000000u) ? ~u : (u | 0x80000000u);
}

__global__ void zero_hist_kernel() {
    int i = blockIdx.x * blockDim.x + threadIdx.x;
    if (i < 2 * 65536) (&g_hist[0][0])[i] = 0u;
}

__global__ void hist_hi_kernel() {
    for (int i = blockIdx.x * blockDim.x + threadIdx.x; i < 2 * NA; i += gridDim.x * blockDim.x) {
        int b = i / NA;
        unsigned k = f2u(g_scores[i]);
        atomicAdd(&g_hist[b][k >> 16], 1u);
    }
}

__global__ void scan_hi_kernel() {
    int b = blockIdx.x, tid = threadIdx.x;
    __shared__ unsigned ssum[1024];
    unsigned tsum = 0;
    int base = tid * 64;
    for (int i = 0; i < 64; i++) tsum += g_hist[b][base + i];
    ssum[tid] = tsum;
    __syncthreads();
    for (int off = 1; off < 1024; off <<= 1) {
        unsigned v = (tid + off < 1024) ? ssum[tid + off] : 0u;
        __syncthreads();
        ssum[tid] += v;
        __syncthreads();
    }
    unsigned above = ssum[tid] - tsum;   // keys in bins strictly above my range
    if (above < TOPK && above + tsum >= TOPK) {
        unsigned acc = above;
        for (int i = 63; i >= 0; i--) {
            unsigned c = g_hist[b][base + i];
            if (acc + c >= TOPK) { g_selHi[b] = (unsigned)(base + i); g_above[b] = acc; break; }
            acc += c;
        }
    }
}

__global__ void hist_lo_kernel() {
    for (int i = blockIdx.x * blockDim.x + threadIdx.x; i < 2 * NA; i += gridDim.x * blockDim.x) {
        int b = i / NA;
        unsigned k = f2u(g_scores[i]);
        if ((k >> 16) == g_selHi[b]) atomicAdd(&g_hist[b][k & 0xFFFFu], 1u);
    }
}

__global__ void scan_lo_kernel() {
    int b = blockIdx.x, tid = threadIdx.x;
    unsigned Kp = TOPK - g_above[b];
    __shared__ unsigned ssum[1024];
    unsigned tsum = 0;
    int base = tid * 64;
    for (int i = 0; i < 64; i++) tsum += g_hist[b][base + i];
    ssum[tid] = tsum;
    __syncthreads();
    for (int off = 1; off < 1024; off <<= 1) {
        unsigned v = (tid + off < 1024) ? ssum[tid + off] : 0u;
        __syncthreads();
        ssum[tid] += v;
        __syncthreads();
    }
    unsigned above = ssum[tid] - tsum;
    if (above < Kp && above + tsum >= Kp) {
        unsigned acc = above;
        for (int i = 63; i >= 0; i--) {
            unsigned c = g_hist[b][base + i];
            if (acc + c >= Kp) {
                g_T[b] = (g_selHi[b] << 16) | (unsigned)(base + i);
                break;
            }
            acc += c;
        }
    }
    if (tid == 0) g_candCnt[b] = 0;
}

__global__ void compact_kernel() {
    for (int i = blockIdx.x * blockDim.x + threadIdx.x; i < 2 * NA; i += gridDim.x * blockDim.x) {
        int b = i / NA;
        unsigned k = f2u(g_scores[i]);
        if (k >= g_T[b]) {
            int p = atomicAdd(&g_candCnt[b], 1);
            if (p < 2048) {
                unsigned idx = (unsigned)(i - b * NA);
                g_cand[b][p] = ((unsigned long long)k << 32) | (unsigned long long)(~idx);
            }
        }
    }
}

// Bitonic sort of <=2048 candidates, composite key (score desc, index asc)
__global__ void sort_topk_kernel() {
    int b = blockIdx.x, tid = threadIdx.x;
    __shared__ unsigned long long s[2048];
    int n = g_candCnt[b];
    if (n > 2048) n = 2048;
    for (int t = tid; t < 2048; t += 1024) s[t] = (t < n) ? g_cand[b][t] : 0ULL;
    __syncthreads();
    for (int k = 2; k <= 2048; k <<= 1) {
        for (int j = k >> 1; j > 0; j >>= 1) {
            int i = ((tid & ~(j - 1)) << 1) | (tid & (j - 1));
            int p = i | j;
            bool desc = ((i & k) == 0);
            unsigned long long a = s[i], c = s[p];
            if (desc ? (a < c) : (a > c)) { s[i] = c; s[p] = a; }
            __syncthreads();
        }
    }
    if (tid < TOPK) {
        unsigned long long v = s[tid];
        if (v != 0ULL) {
            unsigned idx = ~(unsigned)(v & 0xFFFFFFFFull);
            g_ts[b][tid] = g_scores[(size_t)b * NA + idx];
            g_tb[b][tid] = g_boxes[(size_t)b * NA + idx];
        } else {
            g_ts[b][tid] = -1e9f;
            g_tb[b][tid] = make_float4(0.f, 0.f, 0.f, 0.f);
        }
    }
}

// ---------------- greedy NMS + compaction to (300,5) ----------------
__global__ void nms_out_kernel(float* __restrict__ out) {
    int b = blockIdx.x, j = threadIdx.x;
    __shared__ float sx1[TOPK], sy1[TOPK], sx2[TOPK], sy2[TOPK], sar[TOPK];
    __shared__ int   supp[TOPK];
    __shared__ int   scn[1024];

    float bx1 = 0.f, by1 = 0.f, bx2 = 0.f, by2 = 0.f, barea = 0.f, bscore = -1e9f;
    if (j < TOPK) {
        float4 bb = g_tb[b][j];
        bx1 = bb.x; by1 = bb.y; bx2 = bb.z; by2 = bb.w;
        barea = __fmul_rn(__fsub_rn(bx2, bx1), __fsub_rn(by2, by1));
        bscore = g_ts[b][j];
        sx1[j] = bx1; sy1[j] = by1; sx2[j] = bx2; sy2[j] = by2; sar[j] = barea;
        supp[j] = 0;
    }
    __syncthreads();

    for (int i = 0; i < TOPK; i++) {
        if (!supp[i]) {                       // uniform branch (same smem word for all)
            if (j > i && j < TOPK && !supp[j]) {
                float xx1 = fmaxf(sx1[i], bx1);
                float yy1 = fmaxf(sy1[i], by1);
                float xx2 = fminf(sx2[i], bx2);
                float yy2 = fminf(sy2[i], by2);
                float inter = __fmul_rn(fmaxf(__fsub_rn(xx2, xx1), 0.f),
                                        fmaxf(__fsub_rn(yy2, yy1), 0.f));
                float den = __fadd_rn(__fsub_rn(__fadd_rn(sar[i], barea), inter), 1e-9f);
                float iou = __fdiv_rn(inter, den);
                if (iou > 0.7f) supp[j] = 1;
            }
            __syncthreads();
        }
    }

    int keepf = (j < TOPK && !supp[j] && bscore > -1e8f) ? 1 : 0;

    for (int t = j; t < POST * 5; t += 1024) out[(size_t)b * POST * 5 + t] = 0.f;

    scn[j] = keepf;
    __syncthreads();
    for (int off = 1; off < 1024; off <<= 1) {
        int v = (j >= off) ? scn[j - off] : 0;
        __syncthreads();
        scn[j] += v;
        __syncthreads();
    }
    int rank = scn[j] - keepf;
    if (keepf && rank < POST) {
        float* o = out + (size_t)b * POST * 5 + (size_t)rank * 5;
        o[0] = bx1; o[1] = by1; o[2] = bx2; o[3] = by2; o[4] = bscore;
    }
}

// ---------------- host launcher ----------------
extern "C" void kernel_launch(void* const* d_in, const int* in_sizes, int n_in,
                              void* d_out, int out_size) {
    const float* p[5] = {0, 0, 0, 0, 0};
    const float *convw = 0, *convb = 0, *clsw = 0, *clsb = 0, *boxw = 0, *boxb = 0;
    for (int i = 0; i < n_in; i++) {
        switch (in_sizes[i]) {
            case 33554432: p[0]  = (const float*)d_in[i]; break; // p2 (2,256,256,256)
            case 8388608:  p[1]  = (const float*)d_in[i]; break; // p3
            case 2097152:  p[2]  = (const float*)d_in[i]; break; // p4
            case 524288:   p[3]  = (const float*)d_in[i]; break; // p5
            case 131072:   p[4]  = (const float*)d_in[i]; break; // p6
            case 589824:   convw = (const float*)d_in[i]; break; // (256,256,3,3)
            case 256:      convb = (const float*)d_in[i]; break;
            case 768:      clsw  = (const float*)d_in[i]; break; // (3,256)
            case 3:        clsb  = (const float*)d_in[i]; break;
            case 3072:     boxw  = (const float*)d_in[i]; break; // (12,256)
            case 12:       boxb  = (const float*)d_in[i]; break;
        }
    }

    const int   Hs[5]      = {256, 128, 64, 32, 16};
    const int   strides[5] = {4, 8, 16, 32, 64};
    const float sizes[5]   = {32.f, 64.f, 128.f, 256.f, 512.f};
    const int   offs[5]    = {0, 196608, 245760, 258048, 261120};

    for (int l = 0; l < 5; l++) {
        int H = Hs[l], W = Hs[l];
        dim3 grid((W + 63) / 64, H / 2, 16);
        conv3x3_relu_kernel<<<grid, 256>>>(p[l], convw, convb, H, W);
        int HW = H * W;
        dim3 g2((HW + 255) / 256, 2);
        head_decode_kernel<<<g2, 256>>>(clsw, clsb, boxw, boxb, H, W, strides[l], sizes[l], offs[l]);
    }

    zero_hist_kernel<<<512, 256>>>();
    hist_hi_kernel<<<1024, 256>>>();
    scan_hi_kernel<<<2, 1024>>>();
    zero_hist_kernel<<<512, 256>>>();
    hist_lo_kernel<<<1024, 256>>>();
    scan_lo_kernel<<<2, 1024>>>();
    compact_kernel<<<1024, 256>>>();
    sort_topk_kernel<<<2, 1024>>>();
    nms_out_kernel<<<2, 1024>>>((float*)d_out);
}

// round 5
// speedup vs baseline: 1.0452x; 1.0452x over previous
#include <cuda_runtime.h>
#include <cstdint>

#define NA 261888
#define TOPK 1000
#define POST 300

// ---------------- static scratch (no allocations allowed) ----------------
__device__ float              g_x[(size_t)2 * 256 * 256 * 256]; // conv output, reused per level
__device__ float              g_scores[2 * NA];
__device__ float4             g_boxes[2 * NA];
__device__ unsigned           g_hist[2][65536];
__device__ unsigned           g_selHi[2];
__device__ unsigned           g_above[2];
__device__ unsigned           g_T[2];
__device__ int                g_candCnt[2];
__device__ unsigned long long g_cand[2][2048];
__device__ float              g_ts[2][1024];
__device__ float4             g_tb[2][1024];

// ---------------- f32x2 packed-FMA helpers (Blackwell) ----------------
// fma.rn.f32x2 = two independent round-to-nearest fp32 FMAs in one instr.
// Bitwise identical per lane to FFMA.rn, but uses the full 128-lane fp32 pipe
// (3-reg FFMA issues at rt_SMSP=2 -> only 64 lanes/cyc/SM).
__device__ __forceinline__ unsigned long long pack_dup(float v) {
    unsigned long long r;
    unsigned u = __float_as_uint(v);
    asm("mov.b64 %0, {%1, %1};" : "=l"(r) : "r"(u));
    return r;
}
__device__ __forceinline__ void fma2(unsigned long long& acc,
                                     unsigned long long a,
                                     unsigned long long b) {
    asm("fma.rn.f32x2 %0, %1, %2, %0;" : "+l"(acc) : "l"(a), "l"(b));
}
__device__ __forceinline__ void unpack2(unsigned long long v, float& lo, float& hi) {
    unsigned a, b;
    asm("mov.b64 {%0, %1}, %2;" : "=r"(a), "=r"(b) : "l"(v));
    lo = __uint_as_float(a);
    hi = __uint_as_float(b);
}

// ---------------- XLA-exact sigmoid: 0.5 + 0.5*fast_tanh(0.5*x) ----------------
__device__ __forceinline__ float xla_fast_tanh(float x) {
    const float kBound = 7.90531110763549805f;
    float xc = fminf(fmaxf(x, -kBound), kBound);
    float x2 = __fmul_rn(xc, xc);
    float n = __fadd_rn(__fmul_rn(x2, -2.76076847742355e-16f), 2.00018790482477e-13f);
    n = __fadd_rn(__fmul_rn(x2, n), -8.60467152213735e-11f);
    n = __fadd_rn(__fmul_rn(x2, n),  5.12229709037114e-08f);
    n = __fadd_rn(__fmul_rn(x2, n),  1.48572235717979e-05f);
    n = __fadd_rn(__fmul_rn(x2, n),  6.37261928875436e-04f);
    n = __fadd_rn(__fmul_rn(x2, n),  4.89352455891786e-03f);
    n = __fmul_rn(xc, n);
    float d = __fadd_rn(__fmul_rn(x2, 1.19825839466702e-06f), 1.18534705686654e-04f);
    d = __fadd_rn(__fmul_rn(x2, d), 2.26843463243900e-03f);
    d = __fadd_rn(__fmul_rn(x2, d), 4.89352518554385e-03f);
    float t = __fdiv_rn(n, d);
    return (fabsf(x) < 0.0004f) ? x : t;
}
__device__ __forceinline__ float xla_sigmoid(float l) {
    float t = xla_fast_tanh(__fmul_rn(0.5f, l));
    return __fadd_rn(0.5f, __fmul_rn(0.5f, t));
}

// ---------------- conv 3x3 (256->256) + bias + relu, f32x2 dual-issue ----------------
// Tile: 2 rows x 64 cols x 32 oc, 256 threads. Thread (tx,ty) computes pixels
// (y0+{0,1}, x0+tx) and (y0+{0,1}, x0+32+tx) for oc pairs (2ty, 2ty+1) and
// (2ty+16, 2ty+17). Each accumulator is a packed f32x2 over the oc pair; the
// weight pair comes from one warp-uniform LDS.64, the activation is duplicated
// into both halves. Per-output FMA chain order (ic asc, ky asc, kx asc) is
// IDENTICAL to the round-4 kernel -> bitwise-identical output.
__global__ void __launch_bounds__(256, 2)
conv3x3_relu_kernel(const float* __restrict__ in,
                    const float* __restrict__ w,
                    const float* __restrict__ bias,
                    int H, int W) {
    const int tx  = threadIdx.x & 31;
    const int ty  = threadIdx.x >> 5;
    const int x0  = blockIdx.x * 64;
    const int y0  = blockIdx.y * 2;
    const int b   = blockIdx.z >> 3;
    const int ocb = (blockIdx.z & 7) * 32;

    __shared__ float s_in[8][4][66];
    __shared__ float s_w[8][9][34];   // [ic][k][oc], padded to 34: 8B-aligned pairs,
                                      // conflict-free staging stores (bank step 2)

    // acc2[p][px]: p = oc-pair (2ty+16p, +1), px = r*2 + (0:colA,1:colB)
    unsigned long long acc2[2][4];
#pragma unroll
    for (int p = 0; p < 2; p++)
#pragma unroll
        for (int q = 0; q < 4; q++) acc2[p][q] = 0ULL;

    const float* inB = in + (size_t)b * 256 * H * W;

    for (int icb = 0; icb < 256; icb += 8) {
        for (int e = threadIdx.x; e < 8 * 4 * 66; e += 256) {
            int ic = e / 264; int rem = e % 264; int r = rem / 66; int c = rem % 66;
            int yy = y0 + r - 1; int xx = x0 + c - 1;
            float v = 0.f;
            if (yy >= 0 && yy < H && xx >= 0 && xx < W)
                v = inB[(size_t)(icb + ic) * H * W + (size_t)yy * W + xx];
            s_in[ic][r][c] = v;
        }
        for (int e = threadIdx.x; e < 8 * 32 * 9; e += 256) {
            int oc = e / 72; int rem = e % 72; int ic = rem / 9; int k = rem % 9;
            s_w[ic][k][oc] = w[((size_t)(ocb + oc) * 256 + (size_t)(icb + ic)) * 9 + k];
        }
        __syncthreads();
#pragma unroll
        for (int ic = 0; ic < 8; ic++) {
            // duplicate-packed activations: 4 rows x 3 taps, two columns
            unsigned long long pa[4][3], pb[4][3];
#pragma unroll
            for (int r = 0; r < 4; r++)
#pragma unroll
                for (int c = 0; c < 3; c++) {
                    pa[r][c] = pack_dup(s_in[ic][r][tx + c]);
                    pb[r][c] = pack_dup(s_in[ic][r][tx + 32 + c]);
                }
#pragma unroll
            for (int p = 0; p < 2; p++) {
                const int oc2 = 2 * ty + 16 * p;
#pragma unroll
                for (int k = 0; k < 9; k++) {
                    const int ky = k / 3, kx = k % 3;
                    unsigned long long w2 =
                        *reinterpret_cast<const unsigned long long*>(&s_w[ic][k][oc2]);
                    fma2(acc2[p][0], pa[ky][kx],     w2);
                    fma2(acc2[p][1], pb[ky][kx],     w2);
                    fma2(acc2[p][2], pa[ky + 1][kx], w2);
                    fma2(acc2[p][3], pb[ky + 1][kx], w2);
                }
            }
        }
        __syncthreads();
    }

#pragma unroll
    for (int p = 0; p < 2; p++) {
        const int ocl = ocb + 2 * ty + 16 * p;
        const float bv0 = bias[ocl];
        const float bv1 = bias[ocl + 1];
        float* out0 = g_x + (size_t)(b * 256 + ocl) * H * W;
        float* out1 = out0 + (size_t)H * W;
#pragma unroll
        for (int q = 0; q < 4; q++) {
            float v0, v1;
            unpack2(acc2[p][q], v0, v1);
            int y = y0 + (q >> 1);
            int x = (q & 1) ? (x0 + 32 + tx) : (x0 + tx);
            if (x < W) {
                out0[(size_t)y * W + x] = fmaxf(__fadd_rn(v0, bv0), 0.f);
                out1[(size_t)y * W + x] = fmaxf(__fadd_rn(v1, bv1), 0.f);
            }
        }
    }
}

// ---------------- 1x1 heads + anchor decode + sigmoid + mask ----------------
__global__ void head_decode_kernel(const float* __restrict__ clsw, const float* __restrict__ clsb,
                                   const float* __restrict__ boxw, const float* __restrict__ boxb,
                                   int H, int W, int stride, float asize, int lvl_off) {
    __shared__ float s_cw[3 * 256];
    __shared__ float s_bw[12 * 256];
    for (int e = threadIdx.x; e < 3 * 256; e += blockDim.x) s_cw[e] = clsw[e];
    for (int e = threadIdx.x; e < 12 * 256; e += blockDim.x) s_bw[e] = boxw[e];
    __syncthreads();

    int pix = blockIdx.x * blockDim.x + threadIdx.x;
    int b   = blockIdx.y;
    int HW  = H * W;
    if (pix >= HW) return;

    const float* xp = g_x + (size_t)b * 256 * HW + pix;
    float o[3]  = {0.f, 0.f, 0.f};
    float d[12];
#pragma unroll
    for (int j = 0; j < 12; j++) d[j] = 0.f;

    for (int c = 0; c < 256; c++) {
        float v = xp[(size_t)c * HW];
        o[0] += v * s_cw[c];
        o[1] += v * s_cw[256 + c];
        o[2] += v * s_cw[512 + c];
#pragma unroll
        for (int j = 0; j < 12; j++) d[j] += v * s_bw[j * 256 + c];
    }
#pragma unroll
    for (int a = 0; a < 3; a++) o[a] = __fadd_rn(o[a], clsb[a]);
#pragma unroll
    for (int j = 0; j < 12; j++) d[j] = __fadd_rn(d[j], boxb[j]);

    int yy = pix / W, xx = pix % W;
    float xs = (float)(xx * stride), ys = (float)(yy * stride);
    const float ratios[3] = {0.5f, 1.0f, 2.0f};
#pragma unroll
    for (int a = 0; a < 3; a++) {
        float s  = sqrtf(ratios[a]);
        float hh = __fmul_rn(asize, s);
        float ww = __fdiv_rn(asize, s);
        float ax1 = __fadd_rn(xs, -0.5f * ww);
        float ax2 = __fadd_rn(xs,  0.5f * ww);
        float ay1 = __fadd_rn(ys, -0.5f * hh);
        float ay2 = __fadd_rn(ys,  0.5f * hh);
        float aw = __fsub_rn(ax2, ax1);
        float ah = __fsub_rn(ay2, ay1);
        float ax = __fadd_rn(ax1, 0.5f * aw);
        float ay = __fadd_rn(ay1, 0.5f * ah);
        float dx = d[4 * a], dy = d[4 * a + 1], dw = d[4 * a + 2], dh = d[4 * a + 3];
        float cx = __fadd_rn(__fmul_rn(dx, aw), ax);
        float cy = __fadd_rn(__fmul_rn(dy, ah), ay);
        float pw = __fmul_rn(expf(dw), aw);
        float ph = __fmul_rn(expf(dh), ah);
        float x1 = __fsub_rn(cx, 0.5f * pw);
        float y1 = __fsub_rn(cy, 0.5f * ph);
        float x2 = __fadd_rn(cx, 0.5f * pw);
        float y2 = __fadd_rn(cy, 0.5f * ph);
        x1 = fminf(fmaxf(x1, 0.f), 1024.f);
        y1 = fminf(fmaxf(y1, 0.f), 1024.f);
        x2 = fminf(fmaxf(x2, 0.f), 1024.f);
        y2 = fminf(fmaxf(y2, 0.f), 1024.f);
        float ws = __fsub_rn(x2, x1), hs = __fsub_rn(y2, y1);
        bool valid = (ws >= 1.0f) && (hs >= 1.0f);
        float sc = xla_sigmoid(o[a]);
        float masked = valid ? sc : -1e9f;
        int aidx = lvl_off + pix * 3 + a;
        g_scores[(size_t)b * NA + aidx] = masked;
        g_boxes[(size_t)b * NA + aidx] = make_float4(x1, y1, x2, y2);
    }
}

// ---------------- top-k via 2-pass 16-bit radix select ----------------
__device__ __forceinline__ unsigned f2u(float f) {
    unsigned u = __float_as_uint(f);
    return (u & 0x80000000u) ? ~u : (u | 0x80000000u);
}

__global__ void zero_hist_kernel() {
    int i = blockIdx.x * blockDim.x + threadIdx.x;
    if (i < 2 * 65536) (&g_hist[0][0])[i] = 0u;
}

__global__ void hist_hi_kernel() {
    for (int i = blockIdx.x * blockDim.x + threadIdx.x; i < 2 * NA; i += gridDim.x * blockDim.x) {
        int b = i / NA;
        unsigned k = f2u(g_scores[i]);
        atomicAdd(&g_hist[b][k >> 16], 1u);
    }
}

__global__ void scan_hi_kernel() {
    int b = blockIdx.x, tid = threadIdx.x;
    __shared__ unsigned ssum[1024];
    unsigned tsum = 0;
    int base = tid * 64;
    for (int i = 0; i < 64; i++) tsum += g_hist[b][base + i];
    ssum[tid] = tsum;
    __syncthreads();
    for (int off = 1; off < 1024; off <<= 1) {
        unsigned v = (tid + off < 1024) ? ssum[tid + off] : 0u;
        __syncthreads();
        ssum[tid] += v;
        __syncthreads();
    }
    unsigned above = ssum[tid] - tsum;
    if (above < TOPK && above + tsum >= TOPK) {
        unsigned acc = above;
        for (int i = 63; i >= 0; i--) {
            unsigned c = g_hist[b][base + i];
            if (acc + c >= TOPK) { g_selHi[b] = (unsigned)(base + i); g_above[b] = acc; break; }
            acc += c;
        }
    }
}

__global__ void hist_lo_kernel() {
    for (int i = blockIdx.x * blockDim.x + threadIdx.x; i < 2 * NA; i += gridDim.x * blockDim.x) {
        int b = i / NA;
        unsigned k = f2u(g_scores[i]);
        if ((k >> 16) == g_selHi[b]) atomicAdd(&g_hist[b][k & 0xFFFFu], 1u);
    }
}

__global__ void scan_lo_kernel() {
    int b = blockIdx.x, tid = threadIdx.x;
    unsigned Kp = TOPK - g_above[b];
    __shared__ unsigned ssum[1024];
    unsigned tsum = 0;
    int base = tid * 64;
    for (int i = 0; i < 64; i++) tsum += g_hist[b][base + i];
    ssum[tid] = tsum;
    __syncthreads();
    for (int off = 1; off < 1024; off <<= 1) {
        unsigned v = (tid + off < 1024) ? ssum[tid + off] : 0u;
        __syncthreads();
        ssum[tid] += v;
        __syncthreads();
    }
    unsigned above = ssum[tid] - tsum;
    if (above < Kp && above + tsum >= Kp) {
        unsigned acc = above;
        for (int i = 63; i >= 0; i--) {
            unsigned c = g_hist[b][base + i];
            if (acc + c >= Kp) {
                g_T[b] = (g_selHi[b] << 16) | (unsigned)(base + i);
                break;
            }
            acc += c;
        }
    }
    if (tid == 0) g_candCnt[b] = 0;
}

__global__ void compact_kernel() {
    for (int i = blockIdx.x * blockDim.x + threadIdx.x; i < 2 * NA; i += gridDim.x * blockDim.x) {
        int b = i / NA;
        unsigned k = f2u(g_scores[i]);
        if (k >= g_T[b]) {
            int p = atomicAdd(&g_candCnt[b], 1);
            if (p < 2048) {
                unsigned idx = (unsigned)(i - b * NA);
                g_cand[b][p] = ((unsigned long long)k << 32) | (unsigned long long)(~idx);
            }
        }
    }
}

// Bitonic sort of <=2048 candidates, composite key (score desc, index asc)
__global__ void sort_topk_kernel() {
    int b = blockIdx.x, tid = threadIdx.x;
    __shared__ unsigned long long s[2048];
    int n = g_candCnt[b];
    if (n > 2048) n = 2048;
    for (int t = tid; t < 2048; t += 1024) s[t] = (t < n) ? g_cand[b][t] : 0ULL;
    __syncthreads();
    for (int k = 2; k <= 2048; k <<= 1) {
        for (int j = k >> 1; j > 0; j >>= 1) {
            int i = ((tid & ~(j - 1)) << 1) | (tid & (j - 1));
            int p = i | j;
            bool desc = ((i & k) == 0);
            unsigned long long a = s[i], c = s[p];
            if (desc ? (a < c) : (a > c)) { s[i] = c; s[p] = a; }
            __syncthreads();
        }
    }
    if (tid < TOPK) {
        unsigned long long v = s[tid];
        if (v != 0ULL) {
            unsigned idx = ~(unsigned)(v & 0xFFFFFFFFull);
            g_ts[b][tid] = g_scores[(size_t)b * NA + idx];
            g_tb[b][tid] = g_boxes[(size_t)b * NA + idx];
        } else {
            g_ts[b][tid] = -1e9f;
            g_tb[b][tid] = make_float4(0.f, 0.f, 0.f, 0.f);
        }
    }
}

// ---------------- greedy NMS + compaction to (300,5) ----------------
__global__ void nms_out_kernel(float* __restrict__ out) {
    int b = blockIdx.x, j = threadIdx.x;
    __shared__ float sx1[TOPK], sy1[TOPK], sx2[TOPK], sy2[TOPK], sar[TOPK];
    __shared__ int   supp[TOPK];
    __shared__ int   scn[1024];

    float bx1 = 0.f, by1 = 0.f, bx2 = 0.f, by2 = 0.f, barea = 0.f, bscore = -1e9f;
    if (j < TOPK) {
        float4 bb = g_tb[b][j];
        bx1 = bb.x; by1 = bb.y; bx2 = bb.z; by2 = bb.w;
        barea = __fmul_rn(__fsub_rn(bx2, bx1), __fsub_rn(by2, by1));
        bscore = g_ts[b][j];
        sx1[j] = bx1; sy1[j] = by1; sx2[j] = bx2; sy2[j] = by2; sar[j] = barea;
        supp[j] = 0;
    }
    __syncthreads();

    for (int i = 0; i < TOPK; i++) {
        if (!supp[i]) {
            if (j > i && j < TOPK && !supp[j]) {
                float xx1 = fmaxf(sx1[i], bx1);
                float yy1 = fmaxf(sy1[i], by1);
                float xx2 = fminf(sx2[i], bx2);
                float yy2 = fminf(sy2[i], by2);
                float inter = __fmul_rn(fmaxf(__fsub_rn(xx2, xx1), 0.f),
                                        fmaxf(__fsub_rn(yy2, yy1), 0.f));
                float den = __fadd_rn(__fsub_rn(__fadd_rn(sar[i], barea), inter), 1e-9f);
                float iou = __fdiv_rn(inter, den);
                if (iou > 0.7f) supp[j] = 1;
            }
            __syncthreads();
        }
    }

    int keepf = (j < TOPK && !supp[j] && bscore > -1e8f) ? 1 : 0;

    for (int t = j; t < POST * 5; t += 1024) out[(size_t)b * POST * 5 + t] = 0.f;

    scn[j] = keepf;
    __syncthreads();
    for (int off = 1; off < 1024; off <<= 1) {
        int v = (j >= off) ? scn[j - off] : 0;
        __syncthreads();
        scn[j] += v;
        __syncthreads();
    }
    int rank = scn[j] - keepf;
    if (keepf && rank < POST) {
        float* o = out + (size_t)b * POST * 5 + (size_t)rank * 5;
        o[0] = bx1; o[1] = by1; o[2] = bx2; o[3] = by2; o[4] = bscore;
    }
}

// ---------------- host launcher ----------------
extern "C" void kernel_launch(void* const* d_in, const int* in_sizes, int n_in,
                              void* d_out, int out_size) {
    const float* p[5] = {0, 0, 0, 0, 0};
    const float *convw = 0, *convb = 0, *clsw = 0, *clsb = 0, *boxw = 0, *boxb = 0;
    for (int i = 0; i < n_in; i++) {
        switch (in_sizes[i]) {
            case 33554432: p[0]  = (const float*)d_in[i]; break; // p2 (2,256,256,256)
            case 8388608:  p[1]  = (const float*)d_in[i]; break; // p3
            case 2097152:  p[2]  = (const float*)d_in[i]; break; // p4
            case 524288:   p[3]  = (const float*)d_in[i]; break; // p5
            case 131072:   p[4]  = (const float*)d_in[i]; break; // p6
            case 589824:   convw = (const float*)d_in[i]; break; // (256,256,3,3)
            case 256:      convb = (const float*)d_in[i]; break;
            case 768:      clsw  = (const float*)d_in[i]; break; // (3,256)
            case 3:        clsb  = (const float*)d_in[i]; break;
            case 3072:     boxw  = (const float*)d_in[i]; break; // (12,256)
            case 12:       boxb  = (const float*)d_in[i]; break;
        }
    }

    const int   Hs[5]      = {256, 128, 64, 32, 16};
    const int   strides[5] = {4, 8, 16, 32, 64};
    const float sizes[5]   = {32.f, 64.f, 128.f, 256.f, 512.f};
    const int   offs[5]    = {0, 196608, 245760, 258048, 261120};

    for (int l = 0; l < 5; l++) {
        int H = Hs[l], W = Hs[l];
        dim3 grid((W + 63) / 64, H / 2, 16);
        conv3x3_relu_kernel<<<grid, 256>>>(p[l], convw, convb, H, W);
        int HW = H * W;
        dim3 g2((HW + 255) / 256, 2);
        head_decode_kernel<<<g2, 256>>>(clsw, clsb, boxw, boxb, H, W, strides[l], sizes[l], offs[l]);
    }

    zero_hist_kernel<<<512, 256>>>();
    hist_hi_kernel<<<1024, 256>>>();
    scan_hi_kernel<<<2, 1024>>>();
    zero_hist_kernel<<<512, 256>>>();
    hist_lo_kernel<<<1024, 256>>>();
    scan_lo_kernel<<<2, 1024>>>();
    compact_kernel<<<1024, 256>>>();
    sort_topk_kernel<<<2, 1024>>>();
    nms_out_kernel<<<2, 1024>>>((float*)d_out);
}

// round 6
// speedup vs baseline: 1.1568x; 1.1067x over previous
#include <cuda_runtime.h>
#include <cstdint>

#define NA 261888
#define TOPK 1000
#define POST 300

// ---------------- static scratch (no allocations allowed) ----------------
__device__ float              g_x[(size_t)2 * 256 * 256 * 256]; // conv output, reused per level
__device__ float              g_scores[2 * NA];
__device__ float4             g_boxes[2 * NA];
__device__ unsigned           g_hist[2][65536];
__device__ unsigned           g_selHi[2];
__device__ unsigned           g_above[2];
__device__ unsigned           g_T[2];
__device__ int                g_candCnt[2];
__device__ unsigned long long g_cand[2][2048];
__device__ float              g_ts[2][1024];
__device__ float4             g_tb[2][1024];

// ---------------- f32x2 packed-FMA helpers (Blackwell) ----------------
__device__ __forceinline__ unsigned long long pack_dup(float v) {
    unsigned long long r;
    unsigned u = __float_as_uint(v);
    asm("mov.b64 %0, {%1, %1};" : "=l"(r) : "r"(u));
    return r;
}
__device__ __forceinline__ void fma2(unsigned long long& acc,
                                     unsigned long long a,
                                     unsigned long long b) {
    asm("fma.rn.f32x2 %0, %1, %2, %0;" : "+l"(acc) : "l"(a), "l"(b));
}
__device__ __forceinline__ void unpack2(unsigned long long v, float& lo, float& hi) {
    unsigned a, b;
    asm("mov.b64 {%0, %1}, %2;" : "=r"(a), "=r"(b) : "l"(v));
    lo = __uint_as_float(a);
    hi = __uint_as_float(b);
}

// ---------------- XLA-exact sigmoid: 0.5 + 0.5*fast_tanh(0.5*x) ----------------
__device__ __forceinline__ float xla_fast_tanh(float x) {
    const float kBound = 7.90531110763549805f;
    float xc = fminf(fmaxf(x, -kBound), kBound);
    float x2 = __fmul_rn(xc, xc);
    float n = __fadd_rn(__fmul_rn(x2, -2.76076847742355e-16f), 2.00018790482477e-13f);
    n = __fadd_rn(__fmul_rn(x2, n), -8.60467152213735e-11f);
    n = __fadd_rn(__fmul_rn(x2, n),  5.12229709037114e-08f);
    n = __fadd_rn(__fmul_rn(x2, n),  1.48572235717979e-05f);
    n = __fadd_rn(__fmul_rn(x2, n),  6.37261928875436e-04f);
    n = __fadd_rn(__fmul_rn(x2, n),  4.89352455891786e-03f);
    n = __fmul_rn(xc, n);
    float d = __fadd_rn(__fmul_rn(x2, 1.19825839466702e-06f), 1.18534705686654e-04f);
    d = __fadd_rn(__fmul_rn(x2, d), 2.26843463243900e-03f);
    d = __fadd_rn(__fmul_rn(x2, d), 4.89352518554385e-03f);
    float t = __fdiv_rn(n, d);
    return (fabsf(x) < 0.0004f) ? x : t;
}
__device__ __forceinline__ float xla_sigmoid(float l) {
    float t = xla_fast_tanh(__fmul_rn(0.5f, l));
    return __fadd_rn(0.5f, __fmul_rn(0.5f, t));
}

// ---------------- conv 3x3 (256->256) + bias + relu ----------------
// Tile: 2 rows x 64 cols x 64 oc per block, 256 threads (8 warps).
// Thread (tx, ty): pixels (y0+{0,1}, x0+{tx, tx+32}), oc = ocb + 8*ty + {0..7}.
// Activations staged DUPLICATED in smem ({v,v} per 8B slot) so an f32x2
// activation operand is one LDS.64 (no pack MOVs). Weights staged [ic][k][oc]
// so one LDS.128 (ulonglong2) yields two f32x2 weight pairs. Per-output FMA
// chain order (ic asc, ky asc, kx asc) identical to round 4/5 -> bitwise-same.
__global__ void __launch_bounds__(256, 2)
conv3x3_relu_kernel(const float* __restrict__ in,
                    const float* __restrict__ w,
                    const float* __restrict__ bias,
                    int H, int W) {
    const int tx  = threadIdx.x & 31;
    const int ty  = threadIdx.x >> 5;
    const int x0  = blockIdx.x * 64;
    const int y0  = blockIdx.y * 2;
    const int b   = blockIdx.z >> 2;
    const int ocb = (blockIdx.z & 3) * 64;

    __shared__ unsigned long long s_in2[8][4][66];  // duplicated {v,v}
    __shared__ float              s_w[8][9][68];    // [ic][k][oc], 272B rows (16B mult.)

    // acc2[op][q]: op = oc pair (8ty+2op, +1); q = (row<<1)|colhalf
    unsigned long long acc2[4][4];
#pragma unroll
    for (int i = 0; i < 4; i++)
#pragma unroll
        for (int j = 0; j < 4; j++) acc2[i][j] = 0ULL;

    const float* inB = in + (size_t)b * 256 * H * W;

    for (int icb = 0; icb < 256; icb += 8) {
        // stage activations, duplicated
        for (int e = threadIdx.x; e < 8 * 4 * 66; e += 256) {
            int ic = e / 264; int rem = e % 264; int r = rem / 66; int c = rem % 66;
            int yy = y0 + r - 1; int xx = x0 + c - 1;
            float v = 0.f;
            if (yy >= 0 && yy < H && xx >= 0 && xx < W)
                v = inB[(size_t)(icb + ic) * H * W + (size_t)yy * W + xx];
            s_in2[ic][r][c] = pack_dup(v);
        }
        // stage weights [ic][k][oc]
        for (int e = threadIdx.x; e < 8 * 64 * 9; e += 256) {
            int oc = e / 72; int rem = e % 72; int ic = rem / 9; int k = rem % 9;
            s_w[ic][k][oc] = w[((size_t)(ocb + oc) * 256 + (size_t)(icb + ic)) * 9 + k];
        }
        __syncthreads();
#pragma unroll
        for (int ic = 0; ic < 8; ic++) {
            // activation pairs: 4 rows x 3 taps, two column halves (one LDS.64 each)
            unsigned long long pa[4][3], pb[4][3];
#pragma unroll
            for (int r = 0; r < 4; r++)
#pragma unroll
                for (int c = 0; c < 3; c++) {
                    pa[r][c] = s_in2[ic][r][tx + c];
                    pb[r][c] = s_in2[ic][r][tx + 32 + c];
                }
#pragma unroll
            for (int k = 0; k < 9; k++) {
                const int ky = k / 3, kx = k % 3;
                // 8 oc weights as two LDS.128 -> four f32x2 pairs
                ulonglong2 wv0 = *reinterpret_cast<const ulonglong2*>(&s_w[ic][k][8 * ty]);
                ulonglong2 wv1 = *reinterpret_cast<const ulonglong2*>(&s_w[ic][k][8 * ty + 4]);
                fma2(acc2[0][0], pa[ky][kx],     wv0.x);
                fma2(acc2[0][1], pb[ky][kx],     wv0.x);
                fma2(acc2[0][2], pa[ky + 1][kx], wv0.x);
                fma2(acc2[0][3], pb[ky + 1][kx], wv0.x);
                fma2(acc2[1][0], pa[ky][kx],     wv0.y);
                fma2(acc2[1][1], pb[ky][kx],     wv0.y);
                fma2(acc2[1][2], pa[ky + 1][kx], wv0.y);
                fma2(acc2[1][3], pb[ky + 1][kx], wv0.y);
                fma2(acc2[2][0], pa[ky][kx],     wv1.x);
                fma2(acc2[2][1], pb[ky][kx],     wv1.x);
                fma2(acc2[2][2], pa[ky + 1][kx], wv1.x);
                fma2(acc2[2][3], pb[ky + 1][kx], wv1.x);
                fma2(acc2[3][0], pa[ky][kx],     wv1.y);
                fma2(acc2[3][1], pb[ky][kx],     wv1.y);
                fma2(acc2[3][2], pa[ky + 1][kx], wv1.y);
                fma2(acc2[3][3], pb[ky + 1][kx], wv1.y);
            }
        }
        __syncthreads();
    }

#pragma unroll
    for (int op = 0; op < 4; op++) {
        const int ocl = ocb + 8 * ty + 2 * op;
        const float bv0 = bias[ocl];
        const float bv1 = bias[ocl + 1];
        float* out0 = g_x + (size_t)(b * 256 + ocl) * H * W;
        float* out1 = out0 + (size_t)H * W;
#pragma unroll
        for (int q = 0; q < 4; q++) {
            float v0, v1;
            unpack2(acc2[op][q], v0, v1);
            int y = y0 + (q >> 1);
            int x = (q & 1) ? (x0 + 32 + tx) : (x0 + tx);
            if (x < W) {
                out0[(size_t)y * W + x] = fmaxf(__fadd_rn(v0, bv0), 0.f);
                out1[(size_t)y * W + x] = fmaxf(__fadd_rn(v1, bv1), 0.f);
            }
        }
    }
}

// ---------------- 1x1 heads + anchor decode + sigmoid + mask ----------------
// 4 pixels per thread via float4 LDG.128 (4x MLP; per-pixel c-ascending
// accumulation order unchanged -> bitwise identical).
__global__ void head_decode_kernel(const float* __restrict__ clsw, const float* __restrict__ clsb,
                                   const float* __restrict__ boxw, const float* __restrict__ boxb,
                                   int H, int W, int stride, float asize, int lvl_off) {
    __shared__ float s_cw[3 * 256];
    __shared__ float s_bw[12 * 256];
    for (int e = threadIdx.x; e < 3 * 256; e += blockDim.x) s_cw[e] = clsw[e];
    for (int e = threadIdx.x; e < 12 * 256; e += blockDim.x) s_bw[e] = boxw[e];
    __syncthreads();

    int HW   = H * W;
    int pix4 = blockIdx.x * blockDim.x + threadIdx.x;
    int b    = blockIdx.y;
    if (pix4 * 4 >= HW) return;
    int base = pix4 * 4;                         // HW is a multiple of 4 at every level

    const float4* xp = reinterpret_cast<const float4*>(g_x + (size_t)b * 256 * HW + base);
    float o[3][4];
    float d[12][4];
#pragma unroll
    for (int a = 0; a < 3; a++)
#pragma unroll
        for (int s = 0; s < 4; s++) o[a][s] = 0.f;
#pragma unroll
    for (int j = 0; j < 12; j++)
#pragma unroll
        for (int s = 0; s < 4; s++) d[j][s] = 0.f;

    for (int c = 0; c < 256; c++) {
        float4 v = xp[(size_t)c * (HW >> 2)];
        float vv[4] = {v.x, v.y, v.z, v.w};
#pragma unroll
        for (int a = 0; a < 3; a++) {
            float wv = s_cw[a * 256 + c];
#pragma unroll
            for (int s = 0; s < 4; s++) o[a][s] += vv[s] * wv;
        }
#pragma unroll
        for (int j = 0; j < 12; j++) {
            float wv = s_bw[j * 256 + c];
#pragma unroll
            for (int s = 0; s < 4; s++) d[j][s] += vv[s] * wv;
        }
    }
#pragma unroll
    for (int a = 0; a < 3; a++)
#pragma unroll
        for (int s = 0; s < 4; s++) o[a][s] = __fadd_rn(o[a][s], clsb[a]);
#pragma unroll
    for (int j = 0; j < 12; j++)
#pragma unroll
        for (int s = 0; s < 4; s++) d[j][s] = __fadd_rn(d[j][s], boxb[j]);

    const float ratios[3] = {0.5f, 1.0f, 2.0f};
#pragma unroll
    for (int s = 0; s < 4; s++) {
        int pix = base + s;
        int yy = pix / W, xx = pix % W;
        float xs = (float)(xx * stride), ys = (float)(yy * stride);
#pragma unroll
        for (int a = 0; a < 3; a++) {
            float sq = sqrtf(ratios[a]);
            float hh = __fmul_rn(asize, sq);
            float ww = __fdiv_rn(asize, sq);
            float ax1 = __fadd_rn(xs, -0.5f * ww);
            float ax2 = __fadd_rn(xs,  0.5f * ww);
            float ay1 = __fadd_rn(ys, -0.5f * hh);
            float ay2 = __fadd_rn(ys,  0.5f * hh);
            float aw = __fsub_rn(ax2, ax1);
            float ah = __fsub_rn(ay2, ay1);
            float ax = __fadd_rn(ax1, 0.5f * aw);
            float ay = __fadd_rn(ay1, 0.5f * ah);
            float dx = d[4 * a][s], dy = d[4 * a + 1][s];
            float dw = d[4 * a + 2][s], dh = d[4 * a + 3][s];
            float cx = __fadd_rn(__fmul_rn(dx, aw), ax);
            float cy = __fadd_rn(__fmul_rn(dy, ah), ay);
            float pw = __fmul_rn(expf(dw), aw);
            float ph = __fmul_rn(expf(dh), ah);
            float x1 = __fsub_rn(cx, 0.5f * pw);
            float y1 = __fsub_rn(cy, 0.5f * ph);
            float x2 = __fadd_rn(cx, 0.5f * pw);
            float y2 = __fadd_rn(cy, 0.5f * ph);
            x1 = fminf(fmaxf(x1, 0.f), 1024.f);
            y1 = fminf(fmaxf(y1, 0.f), 1024.f);
            x2 = fminf(fmaxf(x2, 0.f), 1024.f);
            y2 = fminf(fmaxf(y2, 0.f), 1024.f);
            float ws = __fsub_rn(x2, x1), hs = __fsub_rn(y2, y1);
            bool valid = (ws >= 1.0f) && (hs >= 1.0f);
            float sc = xla_sigmoid(o[a][s]);
            float masked = valid ? sc : -1e9f;
            int aidx = lvl_off + pix * 3 + a;
            g_scores[(size_t)b * NA + aidx] = masked;
            g_boxes[(size_t)b * NA + aidx] = make_float4(x1, y1, x2, y2);
        }
    }
}

// ---------------- top-k via 2-pass 16-bit radix select ----------------
__device__ __forceinline__ unsigned f2u(float f) {
    unsigned u = __float_as_uint(f);
    return (u & 0x80000000u) ? ~u : (u | 0x80000000u);
}

__global__ void zero_hist_kernel() {
    int i = blockIdx.x * blockDim.x + threadIdx.x;
    if (i < 2 * 65536) (&g_hist[0][0])[i] = 0u;
}

__global__ void hist_hi_kernel() {
    for (int i = blockIdx.x * blockDim.x + threadIdx.x; i < 2 * NA; i += gridDim.x * blockDim.x) {
        int b = i / NA;
        unsigned k = f2u(g_scores[i]);
        atomicAdd(&g_hist[b][k >> 16], 1u);
    }
}

__global__ void scan_hi_kernel() {
    int b = blockIdx.x, tid = threadIdx.x;
    __shared__ unsigned ssum[1024];
    unsigned tsum = 0;
    int base = tid * 64;
    for (int i = 0; i < 64; i++) tsum += g_hist[b][base + i];
    ssum[tid] = tsum;
    __syncthreads();
    for (int off = 1; off < 1024; off <<= 1) {
        unsigned v = (tid + off < 1024) ? ssum[tid + off] : 0u;
        __syncthreads();
        ssum[tid] += v;
        __syncthreads();
    }
    unsigned above = ssum[tid] - tsum;
    if (above < TOPK && above + tsum >= TOPK) {
        unsigned acc = above;
        for (int i = 63; i >= 0; i--) {
            unsigned c = g_hist[b][base + i];
            if (acc + c >= TOPK) { g_selHi[b] = (unsigned)(base + i); g_above[b] = acc; break; }
            acc += c;
        }
    }
}

__global__ void hist_lo_kernel() {
    for (int i = blockIdx.x * blockDim.x + threadIdx.x; i < 2 * NA; i += gridDim.x * blockDim.x) {
        int b = i / NA;
        unsigned k = f2u(g_scores[i]);
        if ((k >> 16) == g_selHi[b]) atomicAdd(&g_hist[b][k & 0xFFFFu], 1u);
    }
}

__global__ void scan_lo_kernel() {
    int b = blockIdx.x, tid = threadIdx.x;
    unsigned Kp = TOPK - g_above[b];
    __shared__ unsigned ssum[1024];
    unsigned tsum = 0;
    int base = tid * 64;
    for (int i = 0; i < 64; i++) tsum += g_hist[b][base + i];
    ssum[tid] = tsum;
    __syncthreads();
    for (int off = 1; off < 1024; off <<= 1) {
        unsigned v = (tid + off < 1024) ? ssum[tid + off] : 0u;
        __syncthreads();
        ssum[tid] += v;
        __syncthreads();
    }
    unsigned above = ssum[tid] - tsum;
    if (above < Kp && above + tsum >= Kp) {
        unsigned acc = above;
        for (int i = 63; i >= 0; i--) {
            unsigned c = g_hist[b][base + i];
            if (acc + c >= Kp) {
                g_T[b] = (g_selHi[b] << 16) | (unsigned)(base + i);
                break;
            }
            acc += c;
        }
    }
    if (tid == 0) g_candCnt[b] = 0;
}

__global__ void compact_kernel() {
    for (int i = blockIdx.x * blockDim.x + threadIdx.x; i < 2 * NA; i += gridDim.x * blockDim.x) {
        int b = i / NA;
        unsigned k = f2u(g_scores[i]);
        if (k >= g_T[b]) {
            int p = atomicAdd(&g_candCnt[b], 1);
            if (p < 2048) {
                unsigned idx = (unsigned)(i - b * NA);
                g_cand[b][p] = ((unsigned long long)k << 32) | (unsigned long long)(~idx);
            }
        }
    }
}

// Bitonic sort of <=2048 candidates, composite key (score desc, index asc)
__global__ void sort_topk_kernel() {
    int b = blockIdx.x, tid = threadIdx.x;
    __shared__ unsigned long long s[2048];
    int n = g_candCnt[b];
    if (n > 2048) n = 2048;
    for (int t = tid; t < 2048; t += 1024) s[t] = (t < n) ? g_cand[b][t] : 0ULL;
    __syncthreads();
    for (int k = 2; k <= 2048; k <<= 1) {
        for (int j = k >> 1; j > 0; j >>= 1) {
            int i = ((tid & ~(j - 1)) << 1) | (tid & (j - 1));
            int p = i | j;
            bool desc = ((i & k) == 0);
            unsigned long long a = s[i], c = s[p];
            if (desc ? (a < c) : (a > c)) { s[i] = c; s[p] = a; }
            __syncthreads();
        }
    }
    if (tid < TOPK) {
        unsigned long long v = s[tid];
        if (v != 0ULL) {
            unsigned idx = ~(unsigned)(v & 0xFFFFFFFFull);
            g_ts[b][tid] = g_scores[(size_t)b * NA + idx];
            g_tb[b][tid] = g_boxes[(size_t)b * NA + idx];
        } else {
            g_ts[b][tid] = -1e9f;
            g_tb[b][tid] = make_float4(0.f, 0.f, 0.f, 0.f);
        }
    }
}

// ---------------- greedy NMS + compaction to (300,5) ----------------
__global__ void nms_out_kernel(float* __restrict__ out) {
    int b = blockIdx.x, j = threadIdx.x;
    __shared__ float sx1[TOPK], sy1[TOPK], sx2[TOPK], sy2[TOPK], sar[TOPK];
    __shared__ int   supp[TOPK];
    __shared__ int   scn[1024];

    float bx1 = 0.f, by1 = 0.f, bx2 = 0.f, by2 = 0.f, barea = 0.f, bscore = -1e9f;
    if (j < TOPK) {
        float4 bb = g_tb[b][j];
        bx1 = bb.x; by1 = bb.y; bx2 = bb.z; by2 = bb.w;
        barea = __fmul_rn(__fsub_rn(bx2, bx1), __fsub_rn(by2, by1));
        bscore = g_ts[b][j];
        sx1[j] = bx1; sy1[j] = by1; sx2[j] = bx2; sy2[j] = by2; sar[j] = barea;
        supp[j] = 0;
    }
    __syncthreads();

    for (int i = 0; i < TOPK; i++) {
        if (!supp[i]) {
            if (j > i && j < TOPK && !supp[j]) {
                float xx1 = fmaxf(sx1[i], bx1);
                float yy1 = fmaxf(sy1[i], by1);
                float xx2 = fminf(sx2[i], bx2);
                float yy2 = fminf(sy2[i], by2);
                float inter = __fmul_rn(fmaxf(__fsub_rn(xx2, xx1), 0.f),
                                        fmaxf(__fsub_rn(yy2, yy1), 0.f));
                float den = __fadd_rn(__fsub_rn(__fadd_rn(sar[i], barea), inter), 1e-9f);
                float iou = __fdiv_rn(inter, den);
                if (iou > 0.7f) supp[j] = 1;
            }
            __syncthreads();
        }
    }

    int keepf = (j < TOPK && !supp[j] && bscore > -1e8f) ? 1 : 0;

    for (int t = j; t < POST * 5; t += 1024) out[(size_t)b * POST * 5 + t] = 0.f;

    scn[j] = keepf;
    __syncthreads();
    for (int off = 1; off < 1024; off <<= 1) {
        int v = (j >= off) ? scn[j - off] : 0;
        __syncthreads();
        scn[j] += v;
        __syncthreads();
    }
    int rank = scn[j] - keepf;
    if (keepf && rank < POST) {
        float* o = out + (size_t)b * POST * 5 + (size_t)rank * 5;
        o[0] = bx1; o[1] = by1; o[2] = bx2; o[3] = by2; o[4] = bscore;
    }
}

// ---------------- host launcher ----------------
extern "C" void kernel_launch(void* const* d_in, const int* in_sizes, int n_in,
                              void* d_out, int out_size) {
    const float* p[5] = {0, 0, 0, 0, 0};
    const float *convw = 0, *convb = 0, *clsw = 0, *clsb = 0, *boxw = 0, *boxb = 0;
    for (int i = 0; i < n_in; i++) {
        switch (in_sizes[i]) {
            case 33554432: p[0]  = (const float*)d_in[i]; break; // p2 (2,256,256,256)
            case 8388608:  p[1]  = (const float*)d_in[i]; break; // p3
            case 2097152:  p[2]  = (const float*)d_in[i]; break; // p4
            case 524288:   p[3]  = (const float*)d_in[i]; break; // p5
            case 131072:   p[4]  = (const float*)d_in[i]; break; // p6
            case 589824:   convw = (const float*)d_in[i]; break; // (256,256,3,3)
            case 256:      convb = (const float*)d_in[i]; break;
            case 768:      clsw  = (const float*)d_in[i]; break; // (3,256)
            case 3:        clsb  = (const float*)d_in[i]; break;
            case 3072:     boxw  = (const float*)d_in[i]; break; // (12,256)
            case 12:       boxb  = (const float*)d_in[i]; break;
        }
    }

    const int   Hs[5]      = {256, 128, 64, 32, 16};
    const int   strides[5] = {4, 8, 16, 32, 64};
    const float sizes[5]   = {32.f, 64.f, 128.f, 256.f, 512.f};
    const int   offs[5]    = {0, 196608, 245760, 258048, 261120};

    for (int l = 0; l < 5; l++) {
        int H = Hs[l], W = Hs[l];
        dim3 grid((W + 63) / 64, H / 2, 8);
        conv3x3_relu_kernel<<<grid, 256>>>(p[l], convw, convb, H, W);
        int HW = H * W;
        int nt4 = HW / 4;
        dim3 g2((nt4 + 255) / 256, 2);
        head_decode_kernel<<<g2, 256>>>(clsw, clsb, boxw, boxb, H, W, strides[l], sizes[l], offs[l]);
    }

    zero_hist_kernel<<<512, 256>>>();
    hist_hi_kernel<<<1024, 256>>>();
    scan_hi_kernel<<<2, 1024>>>();
    zero_hist_kernel<<<512, 256>>>();
    hist_lo_kernel<<<1024, 256>>>();
    scan_lo_kernel<<<2, 1024>>>();
    compact_kernel<<<1024, 256>>>();
    sort_topk_kernel<<<2, 1024>>>();
    nms_out_kernel<<<2, 1024>>>((float*)d_out);
}